// round 4
// baseline (speedup 1.0000x reference)
#include <cuda_runtime.h>
#include <cuda_bf16.h>
#include <math.h>

// ---------------- device scratch (zeroed at module load; OR-updates idempotent across replays) ----
__device__ unsigned int g_present[128];   // bit i => object i present in prev frame t
__device__ unsigned int g_has0[4];        // bit t => some cell unchanged between frames t,t+1
__device__ unsigned int g_has1[4];        // bit t => some cell changed
__device__ int g_t1;                      // ticket 1
__device__ int g_t2;                      // ticket 2 (fallback path)
__device__ int g_status;                  // 0 = unknown, 1 = resolved, 2 = need full scan
__device__ int g_ack;                     // blocks that finished after observing status

// ---------------- cm: masked accumulation + sigmoid, one block / 256 threads ----------------
__device__ __forceinline__ void cm_compute(const float* __restrict__ causal,
                                           float* __restrict__ out, int tid) {
    __shared__ unsigned sp[128];
    __shared__ unsigned sh0c[4], sh1c[4];
    __shared__ float inc0[32], inc1[32];

    if (tid < 127) sp[tid] = __ldcg(&g_present[tid]);
    if (tid < 4)  { sh0c[tid] = __ldcg(&g_has0[tid]); sh1c[tid] = __ldcg(&g_has1[tid]); }
    __syncthreads();

    if (tid < 32) {
        int i = tid;
        int c0 = 0, c1 = 0;
        #pragma unroll 4
        for (int t = 0; t < 127; ++t) {
            unsigned pb  = (sp[t] >> i) & 1u;
            unsigned hb0 = (sh0c[t >> 5] >> (t & 31)) & 1u;
            unsigned hb1 = (sh1c[t >> 5] >> (t & 31)) & 1u;
            c0 += (int)(pb & hb0);
            c1 += (int)(pb & hb1);
        }
        inc0[i] = 0.01f * (float)c0;
        inc1[i] = 0.01f * (float)c1;
    }
    __syncthreads();

    #pragma unroll 4
    for (int k = 0; k < 4; ++k) {
        int idx = k * 256 + tid;
        int i = idx >> 5, j = idx & 31;
        float inc = (j == 0) ? inc0[i] : (j == 1) ? inc1[i] : 0.0f;
        if (i == j) inc = 0.0f;
        float x = causal[idx] + inc;
        out[idx] = 1.0f / (1.0f + expf(-x));
    }
}

// ---------------- single fused kernel ----------------
__global__ __launch_bounds__(256) void fused_all(
    const float* __restrict__ state, const float* __restrict__ emb,
    const float* __restrict__ W1,    const float* __restrict__ b1,
    const float* __restrict__ W2,    const float* __restrict__ b2,
    const float* __restrict__ causal, float* __restrict__ out)
{
    __shared__ float comb[8][256];
    __shared__ float h[8][128];
    __shared__ float mech_s[8][3];
    __shared__ int   s_p[8];
    __shared__ int   s_flag;

    const int tid  = threadIdx.x;
    const int blk  = blockIdx.x;
    const int lane = tid & 31;
    const float4* __restrict__ st4 = (const float4*)state;

    // ---- issue sample loads first (blocks 0..126 own frame t = blk) ----
    float4 a0, a1, c0, c1;
    if (blk < 127) {
        const size_t f0 = (size_t)blk * 4096;
        a0 = st4[f0 + tid];
        a1 = st4[f0 + 256 + tid];
        c0 = st4[f0 + 4096 + tid];
        c1 = st4[f0 + 4096 + 256 + tid];
    }

    // ---- MLP staging ----
    for (int idx = tid; idx < 8 * 256; idx += 256) {
        int g = idx >> 8;
        int k = idx & 255;
        int pp = blk * 8 + g;
        int i = pp >> 5, j = pp & 31;
        comb[g][k] = (k < 128) ? emb[i * 128 + k] : emb[j * 128 + (k - 128)];
    }
    if (tid < 8) {
        int pp = blk * 8 + tid;
        int i = pp >> 5, j = pp & 31;
        s_p[tid] = (i == j) ? -1 : (i * 31 + j - (j > i ? 1 : 0));
    }
    __syncthreads();

    const int d  = tid & 127;
    const int g0 = (tid >> 7) * 4;
    float s0 = b1[d], s1 = s0, s2 = s0, s3 = s0;
    #pragma unroll 4
    for (int k = 0; k < 256; ++k) {
        float w = W1[k * 128 + d];
        s0 = fmaf(comb[g0 + 0][k], w, s0);
        s1 = fmaf(comb[g0 + 1][k], w, s1);
        s2 = fmaf(comb[g0 + 2][k], w, s2);
        s3 = fmaf(comb[g0 + 3][k], w, s3);
    }
    h[g0 + 0][d] = fmaxf(s0, 0.0f);
    h[g0 + 1][d] = fmaxf(s1, 0.0f);
    h[g0 + 2][d] = fmaxf(s2, 0.0f);
    h[g0 + 3][d] = fmaxf(s3, 0.0f);
    __syncthreads();

    if (tid < 24) {
        int g = tid / 3, c = tid - g * 3;
        float s = b2[c];
        #pragma unroll 8
        for (int dd = 0; dd < 128; ++dd)
            s = fmaf(h[g][dd], W2[dd * 3 + c], s);
        mech_s[g][c] = s;
    }

    // ---- sampling reduce + mask atomics ----
    if (blk < 127) {
        unsigned m = (1u << (int)a0.x) | (1u << (int)a0.y) | (1u << (int)a0.z) | (1u << (int)a0.w)
                   | (1u << (int)a1.x) | (1u << (int)a1.y) | (1u << (int)a1.z) | (1u << (int)a1.w);
        m = __reduce_or_sync(0xffffffffu, m);
        bool dd = (a0.x != c0.x) || (a0.y != c0.y) || (a0.z != c0.z) || (a0.w != c0.w)
               || (a1.x != c1.x) || (a1.y != c1.y) || (a1.z != c1.z) || (a1.w != c1.w);
        bool ee = (a0.x == c0.x) || (a0.y == c0.y) || (a0.z == c0.z) || (a0.w == c0.w)
               || (a1.x == c1.x) || (a1.y == c1.y) || (a1.z == c1.z) || (a1.w == c1.w);
        bool anyd = __any_sync(0xffffffffu, dd);
        bool anye = __any_sync(0xffffffffu, ee);
        if (lane == 0) {
            atomicOr(&g_present[blk], m);
            unsigned bit = 1u << (blk & 31);
            if (anyd) atomicOr(&g_has1[blk >> 5], bit);
            if (anye) atomicOr(&g_has0[blk >> 5], bit);
        }
    }
    __syncthreads();

    // ---- preds broadcast directly from smem ----
    for (int idx = tid; idx < 127 * 24; idx += 256) {
        int t = idx / 24;
        int r = idx - t * 24;
        int g = r / 3;
        int c = r - g * 3;
        int p = s_p[g];
        if (p >= 0) out[1024 + t * 2976 + p * 3 + c] = mech_s[g][c];
    }

    // ---- ticket 1: last arriver checks resolvedness ----
    __threadfence();
    if (tid == 0) s_flag = (atomicAdd(&g_t1, 1) == 127) ? 1 : 0;
    __syncthreads();
    const bool is_checker = (s_flag == 1);

    int status;
    if (is_checker) {
        if (tid == 0) s_flag = 0;
        __syncthreads();
        bool u = false;
        if (tid < 127)       u = (__ldcg(&g_present[tid]) != 0xFFFFFFFFu);
        else if (tid == 127) u = ((__ldcg(&g_has0[3]) & 0x7FFFFFFFu) != 0x7FFFFFFFu) ||
                                 ((__ldcg(&g_has1[3]) & 0x7FFFFFFFu) != 0x7FFFFFFFu);
        else if (tid < 131)  u = (__ldcg(&g_has0[tid - 128]) != 0xFFFFFFFFu);
        else if (tid < 134)  u = (__ldcg(&g_has1[tid - 131]) != 0xFFFFFFFFu);
        if (u) atomicOr(&s_flag, 1);
        __syncthreads();
        status = s_flag ? 2 : 1;
        if (tid == 0) {
            __threadfence();
            atomicExch(&g_status, status);
        }
        __syncthreads();
    } else {
        if (tid == 0) {
            int v;
            while ((v = __ldcg((const int*)&g_status)) == 0) __nanosleep(32);
            s_flag = v;
        }
        __syncthreads();
        status = s_flag;
        __threadfence();
    }

    if (status == 1) {
        // -------- fast path --------
        if (is_checker) {
            cm_compute(causal, out, tid);
            if (tid == 0) {
                while (__ldcg((const int*)&g_ack) != 127) __nanosleep(32);
                g_t1 = 0; g_t2 = 0; g_ack = 0;
                __threadfence();
                atomicExch(&g_status, 0);
            }
        } else {
            if (tid == 0) atomicAdd(&g_ack, 1);
        }
        return;
    }

    // -------- exact fallback: full scan, 2 float4 columns per thread --------
    {
        __shared__ unsigned sh_present[128];
        __shared__ unsigned sh_h0[4], sh_h1[4];
        if (tid < 128) sh_present[tid] = 0u;
        if (tid < 4) { sh_h0[tid] = 0u; sh_h1[tid] = 0u; }
        __syncthreads();

        for (int rep = 0; rep < 2; ++rep) {
            const int col4 = blk * 512 + rep * 256 + tid;
            const int b    = col4 >> 12;
            const int hw4  = col4 & 4095;
            const size_t base = (size_t)b * 128 * 4096 + hw4;

            float4 pf = st4[base];
            {
                unsigned m = (1u << (int)pf.x) | (1u << (int)pf.y) |
                             (1u << (int)pf.z) | (1u << (int)pf.w);
                m = __reduce_or_sync(0xffffffffu, m);
                if (lane == 0) atomicOr(&sh_present[0], m);
            }
            #pragma unroll 4
            for (int s = 1; s < 128; ++s) {
                float4 f = st4[base + (size_t)s * 4096];
                if (s < 127) {
                    unsigned m = (1u << (int)f.x) | (1u << (int)f.y) |
                                 (1u << (int)f.z) | (1u << (int)f.w);
                    m = __reduce_or_sync(0xffffffffu, m);
                    if (lane == 0) atomicOr(&sh_present[s], m);
                }
                bool dd = (f.x != pf.x) || (f.y != pf.y) || (f.z != pf.z) || (f.w != pf.w);
                bool ee = (f.x == pf.x) || (f.y == pf.y) || (f.z == pf.z) || (f.w == pf.w);
                bool anyd = __any_sync(0xffffffffu, dd);
                bool anye = __any_sync(0xffffffffu, ee);
                if (lane == 0) {
                    int t = s - 1;
                    unsigned bit = 1u << (t & 31);
                    if (anyd) atomicOr(&sh_h1[t >> 5], bit);
                    if (anye) atomicOr(&sh_h0[t >> 5], bit);
                }
                pf = f;
            }
        }
        __syncthreads();
        if (tid < 128) {
            unsigned v = sh_present[tid];
            if (v) atomicOr(&g_present[tid], v);
        } else if (tid < 132) {
            unsigned v = sh_h0[tid - 128];
            if (v) atomicOr(&g_has0[tid - 128], v);
        } else if (tid < 136) {
            unsigned v = sh_h1[tid - 132];
            if (v) atomicOr(&g_has1[tid - 132], v);
        }
    }

    // ---- ticket 2: last block computes cm and resets ----
    __threadfence();
    if (tid == 0) s_flag = (atomicAdd(&g_t2, 1) == 127) ? 1 : 0;
    __syncthreads();
    if (s_flag == 1) {
        __threadfence();
        cm_compute(causal, out, tid);
        if (tid == 0) {
            while (__ldcg((const int*)&g_ack) != 127) __nanosleep(32);
            g_t1 = 0; g_t2 = 0; g_ack = 0;
            __threadfence();
            atomicExch(&g_status, 0);
        }
    } else {
        if (tid == 0) atomicAdd(&g_ack, 1);
    }
}

// ---------------- launch ----------------
extern "C" void kernel_launch(void* const* d_in, const int* in_sizes, int n_in,
                              void* d_out, int out_size) {
    const float* state  = (const float*)d_in[0];
    const float* emb    = (const float*)d_in[1];
    const float* W1     = (const float*)d_in[2];
    const float* b1     = (const float*)d_in[3];
    const float* W2     = (const float*)d_in[4];
    const float* b2     = (const float*)d_in[5];
    const float* causal = (const float*)d_in[6];
    float* out = (float*)d_out;

    fused_all<<<128, 256>>>(state, emb, W1, b1, W2, b2, causal, out);
}